// round 2
// baseline (speedup 1.0000x reference)
#include <cuda_runtime.h>
#include <math.h>

#define H_  16
#define HD_ 64
#define D_  1024
#define B_  2
#define S_  2048
#define MROWS (B_*S_)   // 4096

// Scratch: [B,H,S,HD] fp32, 16 MB each
__device__ float g_q[(size_t)B_*H_*S_*HD_];
__device__ float g_k[(size_t)B_*H_*S_*HD_];
__device__ float g_v[(size_t)B_*H_*S_*HD_];
__device__ float g_att[(size_t)B_*H_*S_*HD_];

// ---------------------------------------------------------------------------
// Projection GEMM: C[m][n] = sum_k A[m*D+k] * W[n*D+k] + bias[n]
// A: [4096, 1024] row-major (Q/K/V input), W: [1024(out), 1024(in)] row-major
// Output written in [B,H,S,HD] layout: out[((b*H+h)*S+s)*HD+e], n = h*HD+e
// Tiles: BM=BN=64, BK=16, 256 threads, 4x4 per thread.
// ---------------------------------------------------------------------------
__global__ void proj_kernel(const float* __restrict__ A,
                            const float* __restrict__ W,
                            const float* __restrict__ bias,
                            int which)
{
    float* out = (which == 0) ? g_q : (which == 1) ? g_k : g_v;

    __shared__ float As[16][68];   // [k][m]
    __shared__ float Bs[16][68];   // [k][n]

    const int bm = blockIdx.y * 64;
    const int bn = blockIdx.x * 64;
    const int tid = threadIdx.x;
    const int ty = tid >> 4, tx = tid & 15;

    float c[4][4] = {};

    for (int k0 = 0; k0 < D_; k0 += 16) {
        {
            int r = tid >> 2;
            int k = (tid & 3) << 2;
            float4 a = *(const float4*)&A[(size_t)(bm + r) * D_ + k0 + k];
            As[k+0][r] = a.x; As[k+1][r] = a.y; As[k+2][r] = a.z; As[k+3][r] = a.w;
            float4 b = *(const float4*)&W[(size_t)(bn + r) * D_ + k0 + k];
            Bs[k+0][r] = b.x; Bs[k+1][r] = b.y; Bs[k+2][r] = b.z; Bs[k+3][r] = b.w;
        }
        __syncthreads();
        #pragma unroll
        for (int k = 0; k < 16; k++) {
            float a[4], b[4];
            #pragma unroll
            for (int i = 0; i < 4; i++) a[i] = As[k][ty*4 + i];
            #pragma unroll
            for (int j = 0; j < 4; j++) b[j] = Bs[k][tx*4 + j];
            #pragma unroll
            for (int i = 0; i < 4; i++)
                #pragma unroll
                for (int j = 0; j < 4; j++)
                    c[i][j] += a[i] * b[j];
        }
        __syncthreads();
    }

    #pragma unroll
    for (int i = 0; i < 4; i++) {
        int m = bm + ty*4 + i;
        int b = m / S_, s = m % S_;
        #pragma unroll
        for (int j = 0; j < 4; j++) {
            int n = bn + tx*4 + j;
            int h = n >> 6, e = n & 63;
            out[(((size_t)(b*H_ + h)*S_ + s))*HD_ + e] = c[i][j] + bias[n];
        }
    }
}

// ---------------------------------------------------------------------------
// Flash-style attention per (b,h): online softmax over 64-wide key blocks.
// Grid: (S/64, B*H), 256 threads (16x16), 4x4 register tile per thread.
// ---------------------------------------------------------------------------
__global__ void attn_kernel()
{
    extern __shared__ float sm[];
    const int STR = 68;
    float* Qs = sm;                 // 64 x 68
    float* Ks = Qs + 64*STR;
    float* Vs = Ks + 64*STR;
    float* Ps = Vs + 64*STR;

    const int bh = blockIdx.y;           // b*H + h
    const int q0 = blockIdx.x * 64;
    const float* qp = g_q + (size_t)bh * S_ * HD_;
    const float* kp = g_k + (size_t)bh * S_ * HD_;
    const float* vp = g_v + (size_t)bh * S_ * HD_;

    const int tid = threadIdx.x;
    const int ty = tid >> 4, tx = tid & 15;
    const float scale = 0.125f;          // HD^-0.5 = 1/8

    // Load Q block, pre-scaled
    for (int f = tid; f < 1024; f += 256) {
        int r = f >> 4, e = (f & 15) << 2;
        float4 v4 = *(const float4*)&qp[(size_t)(q0 + r) * HD_ + e];
        Qs[r*STR + e+0] = v4.x * scale;
        Qs[r*STR + e+1] = v4.y * scale;
        Qs[r*STR + e+2] = v4.z * scale;
        Qs[r*STR + e+3] = v4.w * scale;
    }

    float acc[4][4] = {};
    float mrow[4], lrow[4];
    #pragma unroll
    for (int i = 0; i < 4; i++) { mrow[i] = -1e30f; lrow[i] = 0.0f; }

    for (int kb = 0; kb < S_; kb += 64) {
        __syncthreads();   // protect Ks/Vs/Ps from previous iteration's readers
        for (int f = tid; f < 1024; f += 256) {
            int r = f >> 4, e = (f & 15) << 2;
            *(float4*)&Ks[r*STR + e] = *(const float4*)&kp[(size_t)(kb + r) * HD_ + e];
            *(float4*)&Vs[r*STR + e] = *(const float4*)&vp[(size_t)(kb + r) * HD_ + e];
        }
        __syncthreads();

        // Scores: s[i][j] = Q[row i] . K[col j]
        float s4[4][4] = {};
        #pragma unroll 4
        for (int e = 0; e < 64; e++) {
            float a[4], b[4];
            #pragma unroll
            for (int i = 0; i < 4; i++) a[i] = Qs[(ty*4 + i)*STR + e];
            #pragma unroll
            for (int j = 0; j < 4; j++) b[j] = Ks[(tx*4 + j)*STR + e];
            #pragma unroll
            for (int i = 0; i < 4; i++)
                #pragma unroll
                for (int j = 0; j < 4; j++)
                    s4[i][j] += a[i] * b[j];
        }

        // Online softmax (rows replicated across the 16 tx-threads; lanes 0-15
        // and 16-31 are disjoint ty groups, shfl_xor {8,4,2,1} stays in-group)
        #pragma unroll
        for (int i = 0; i < 4; i++) {
            float bm = fmaxf(fmaxf(s4[i][0], s4[i][1]), fmaxf(s4[i][2], s4[i][3]));
            #pragma unroll
            for (int m = 8; m >= 1; m >>= 1)
                bm = fmaxf(bm, __shfl_xor_sync(0xffffffffu, bm, m));
            float mn    = fmaxf(mrow[i], bm);
            float alpha = __expf(mrow[i] - mn);
            mrow[i] = mn;
            float ls = 0.0f;
            #pragma unroll
            for (int j = 0; j < 4; j++) {
                float p = __expf(s4[i][j] - mn);
                s4[i][j] = p;
                ls += p;
            }
            #pragma unroll
            for (int m = 8; m >= 1; m >>= 1)
                ls += __shfl_xor_sync(0xffffffffu, ls, m);
            lrow[i] = lrow[i] * alpha + ls;
            #pragma unroll
            for (int j = 0; j < 4; j++) {
                acc[i][j] *= alpha;
                Ps[(ty*4 + i)*STR + tx*4 + j] = s4[i][j];
            }
        }
        __syncthreads();

        // acc += P * V
        #pragma unroll 4
        for (int c = 0; c < 64; c++) {
            float p[4], v[4];
            #pragma unroll
            for (int i = 0; i < 4; i++) p[i] = Ps[(ty*4 + i)*STR + c];
            #pragma unroll
            for (int j = 0; j < 4; j++) v[j] = Vs[c*STR + tx*4 + j];
            #pragma unroll
            for (int i = 0; i < 4; i++)
                #pragma unroll
                for (int j = 0; j < 4; j++)
                    acc[i][j] += p[i] * v[j];
        }
    }

    #pragma unroll
    for (int i = 0; i < 4; i++) {
        float inv = 1.0f / lrow[i];
        size_t row = (size_t)bh * S_ * HD_ + (size_t)(q0 + ty*4 + i) * HD_;
        #pragma unroll
        for (int j = 0; j < 4; j++)
            g_att[row + tx*4 + j] = acc[i][j] * inv;
    }
}

// ---------------------------------------------------------------------------
// Output GEMM: out[m*D+n] = sum_k cat[m][k] * Wo[n*D+k] + bo[n]
// cat[m][k] with m=b*S+s, k=h*64+e  ->  g_att[((b*H+h)*S+s)*64+e]
// ---------------------------------------------------------------------------
__global__ void out_kernel(const float* __restrict__ Wo,
                           const float* __restrict__ bo,
                           float* __restrict__ out)
{
    __shared__ float As[16][68];
    __shared__ float Bs[16][68];

    const int bm = blockIdx.y * 64;
    const int bn = blockIdx.x * 64;
    const int tid = threadIdx.x;
    const int ty = tid >> 4, tx = tid & 15;

    float c[4][4] = {};

    for (int k0 = 0; k0 < D_; k0 += 16) {
        {
            int r = tid >> 2;
            int kk = (tid & 3) << 2;
            int m = bm + r;
            int b = m / S_, s = m % S_;
            int k = k0 + kk;
            int h = k >> 6, e = k & 63;       // 4 consecutive e, never cross head
            float4 a = *(const float4*)&g_att[(((size_t)(b*H_ + h)*S_ + s))*HD_ + e];
            As[kk+0][r] = a.x; As[kk+1][r] = a.y; As[kk+2][r] = a.z; As[kk+3][r] = a.w;
            float4 w = *(const float4*)&Wo[(size_t)(bn + r) * D_ + k];
            Bs[kk+0][r] = w.x; Bs[kk+1][r] = w.y; Bs[kk+2][r] = w.z; Bs[kk+3][r] = w.w;
        }
        __syncthreads();
        #pragma unroll
        for (int k = 0; k < 16; k++) {
            float a[4], b[4];
            #pragma unroll
            for (int i = 0; i < 4; i++) a[i] = As[k][ty*4 + i];
            #pragma unroll
            for (int j = 0; j < 4; j++) b[j] = Bs[k][tx*4 + j];
            #pragma unroll
            for (int i = 0; i < 4; i++)
                #pragma unroll
                for (int j = 0; j < 4; j++)
                    c[i][j] += a[i] * b[j];
        }
        __syncthreads();
    }

    #pragma unroll
    for (int i = 0; i < 4; i++) {
        int m = bm + ty*4 + i;
        #pragma unroll
        for (int j = 0; j < 4; j++) {
            int n = bn + tx*4 + j;
            out[(size_t)m * D_ + n] = c[i][j] + bo[n];
        }
    }
}

// ---------------------------------------------------------------------------
extern "C" void kernel_launch(void* const* d_in, const int* in_sizes, int n_in,
                              void* d_out, int out_size)
{
    const float* V  = (const float*)d_in[0];
    const float* K  = (const float*)d_in[1];
    const float* Q  = (const float*)d_in[2];
    const float* Wv = (const float*)d_in[3];
    const float* bv = (const float*)d_in[4];
    const float* Wk = (const float*)d_in[5];
    const float* bk = (const float*)d_in[6];
    const float* Wq = (const float*)d_in[7];
    const float* bq = (const float*)d_in[8];
    const float* Wo = (const float*)d_in[9];
    const float* bo = (const float*)d_in[10];
    float* out = (float*)d_out;

    (void)in_sizes; (void)n_in; (void)out_size;

    // Projections: grid (N/64, M/64)
    dim3 gproj(D_/64, MROWS/64);
    proj_kernel<<<gproj, 256>>>(Q, Wq, bq, 0);
    proj_kernel<<<gproj, 256>>>(K, Wk, bk, 1);
    proj_kernel<<<gproj, 256>>>(V, Wv, bv, 2);

    // Attention
    const int smem = 4 * 64 * 68 * (int)sizeof(float);   // 69632 B
    cudaFuncSetAttribute(attn_kernel, cudaFuncAttributeMaxDynamicSharedMemorySize, smem);
    dim3 gattn(S_/64, B_*H_);
    attn_kernel<<<gattn, 256, smem>>>();

    // Output projection
    dim3 gout(D_/64, MROWS/64);
    out_kernel<<<gout, 256>>>(Wo, bo, out);
}

// round 3
// speedup vs baseline: 1.9427x; 1.9427x over previous
#include <cuda_runtime.h>
#include <math.h>
#include <stdint.h>

#define H_  16
#define HD_ 64
#define D_  1024
#define B_  2
#define S_  2048
#define MROWS (B_*S_)   // 4096

// Scratch (fp32): q/k/v in [B,H,S,HD]; att in concat layout [B*S, D]
__device__ float g_q[(size_t)B_*H_*S_*HD_];
__device__ float g_k[(size_t)B_*H_*S_*HD_];
__device__ float g_v[(size_t)B_*H_*S_*HD_];
__device__ float g_att[(size_t)MROWS*D_];

// ---------------------------------------------------------------------------
// tf32 helpers
// ---------------------------------------------------------------------------
__device__ __forceinline__ uint32_t f2tf(float f) {
    uint32_t r; asm("cvt.rna.tf32.f32 %0, %1;" : "=r"(r) : "f"(f)); return r;
}
__device__ __forceinline__ float f2tff(float f) { return __uint_as_float(f2tf(f)); }
__device__ __forceinline__ float4 cvt4(float4 v) {
    float4 r; r.x=f2tff(v.x); r.y=f2tff(v.y); r.z=f2tff(v.z); r.w=f2tff(v.w); return r;
}
__device__ __forceinline__ float4 cvt4s(float4 v, float s) {
    float4 r; r.x=f2tff(v.x*s); r.y=f2tff(v.y*s); r.z=f2tff(v.z*s); r.w=f2tff(v.w*s); return r;
}

// mma.m16n8k8 tf32: C += A(16x8 row) * B(8x8 col)
__device__ __forceinline__ void mma8(float* c,
    uint32_t a0, uint32_t a1, uint32_t a2, uint32_t a3,
    uint32_t b0, uint32_t b1)
{
    asm volatile(
        "mma.sync.aligned.m16n8k8.row.col.f32.tf32.tf32.f32 "
        "{%0,%1,%2,%3}, {%4,%5,%6,%7}, {%8,%9}, {%0,%1,%2,%3};"
        : "+f"(c[0]), "+f"(c[1]), "+f"(c[2]), "+f"(c[3])
        : "r"(a0), "r"(a1), "r"(a2), "r"(a3), "r"(b0), "r"(b1));
}

// ---------------------------------------------------------------------------
// Generic GEMM: out[m][n] = sum_k A[m*1024+k] * W[n*1024+k] + bias[n]
// A: [4096,1024] row-major, W: [1024,1024] row-major (n-major, k contiguous)
// transform=1: store to [B,H,S,HD] layout (n=h*64+e); transform=0: row-major.
// Block 128x128x32, 256 threads, 8 warps (2 m x 4 n), warp tile 64x32.
// ---------------------------------------------------------------------------
__global__ void __launch_bounds__(256) gemm_tf32(
    const float* __restrict__ A, const float* __restrict__ W,
    const float* __restrict__ bias, float* __restrict__ out, int transform)
{
    __shared__ float As[128*36];
    __shared__ float Bs[128*36];

    const int bm = blockIdx.y * 128;
    const int bn = blockIdx.x * 128;
    const int tid = threadIdx.x;
    const int wid = tid >> 5, lane = tid & 31;
    const int g = lane >> 2, tig = lane & 3;
    const int wm = (wid & 1) * 64;
    const int wn = (wid >> 1) * 32;

    float c[4][4][4] = {};

    const int lrow = tid >> 1;
    const int lcb  = (tid & 1) * 16;

    for (int k0 = 0; k0 < D_; k0 += 32) {
        {
            const float4* ap = (const float4*)&A[(size_t)(bm + lrow) * D_ + k0 + lcb];
            const float4* wp = (const float4*)&W[(size_t)(bn + lrow) * D_ + k0 + lcb];
            #pragma unroll
            for (int j = 0; j < 4; j++) {
                *(float4*)&As[lrow*36 + lcb + j*4] = cvt4(ap[j]);
                *(float4*)&Bs[lrow*36 + lcb + j*4] = cvt4(wp[j]);
            }
        }
        __syncthreads();
        #pragma unroll
        for (int ks = 0; ks < 4; ks++) {
            uint32_t a[4][4], b[4][2];
            #pragma unroll
            for (int mt = 0; mt < 4; mt++) {
                int r = wm + mt*16;
                a[mt][0] = __float_as_uint(As[(r+g  )*36 + ks*8 + tig    ]);
                a[mt][1] = __float_as_uint(As[(r+g+8)*36 + ks*8 + tig    ]);
                a[mt][2] = __float_as_uint(As[(r+g  )*36 + ks*8 + tig + 4]);
                a[mt][3] = __float_as_uint(As[(r+g+8)*36 + ks*8 + tig + 4]);
            }
            #pragma unroll
            for (int nt = 0; nt < 4; nt++) {
                int n = wn + nt*8;
                b[nt][0] = __float_as_uint(Bs[(n+g)*36 + ks*8 + tig    ]);
                b[nt][1] = __float_as_uint(Bs[(n+g)*36 + ks*8 + tig + 4]);
            }
            #pragma unroll
            for (int mt = 0; mt < 4; mt++)
                #pragma unroll
                for (int nt = 0; nt < 4; nt++)
                    mma8(c[mt][nt], a[mt][0], a[mt][1], a[mt][2], a[mt][3],
                         b[nt][0], b[nt][1]);
        }
        __syncthreads();
    }

    #pragma unroll
    for (int mt = 0; mt < 4; mt++) {
        #pragma unroll
        for (int p = 0; p < 2; p++) {
            int row = bm + wm + mt*16 + g + p*8;
            #pragma unroll
            for (int nt = 0; nt < 4; nt++) {
                int col = bn + wn + nt*8 + tig*2;
                float2 v;
                v.x = c[mt][nt][p*2+0] + bias[col];
                v.y = c[mt][nt][p*2+1] + bias[col+1];
                if (transform) {
                    int b_ = row >> 11, s = row & 2047;
                    int h = col >> 6, e = col & 63;
                    *(float2*)&out[(((size_t)(b_*H_ + h)*S_ + s))*HD_ + e] = v;
                } else {
                    *(float2*)&out[(size_t)row * D_ + col] = v;
                }
            }
        }
    }
}

// ---------------------------------------------------------------------------
// Flash attention with tensor cores.
// Block: 256 threads (8 warps), 128 q-rows per block (16 rows/warp).
// K/V blocks of 64. Online softmax on mma C fragments.
// Writes output in concat layout g_att[(b*S+s)*1024 + h*64 + e].
// ---------------------------------------------------------------------------
__global__ void __launch_bounds__(256) attn_tc()
{
    extern __shared__ float sm[];
    float* Qs = sm;              // 128 x 68 (tf32, pre-scaled)
    float* Ps = Qs + 128*68;     // 128 x 68 (tf32 probs)
    float* Ks = Ps + 128*68;     // 64 x 68
    float* Vs = Ks + 64*68;      // 64 x 68

    const int bh = blockIdx.y;
    const int b  = bh >> 4, h = bh & 15;
    const int q0 = blockIdx.x * 128;
    const float* qp = g_q + (size_t)bh * S_ * HD_;
    const float* kp = g_k + (size_t)bh * S_ * HD_;
    const float* vp = g_v + (size_t)bh * S_ * HD_;

    const int tid = threadIdx.x;
    const int wid = tid >> 5, lane = tid & 31;
    const int g = lane >> 2, tig = lane & 3;
    const float scale = 0.125f;   // HD^-0.5

    // Load + scale + cvt Q block (128 x 64)
    {
        int row = tid >> 1;
        int cb  = (tid & 1) * 32;
        const float4* src = (const float4*)&qp[(size_t)(q0 + row) * HD_ + cb];
        #pragma unroll
        for (int j = 0; j < 8; j++)
            *(float4*)&Qs[row*68 + cb + j*4] = cvt4s(src[j], scale);
    }

    float m0 = -1e30f, m1 = -1e30f, l0 = 0.f, l1 = 0.f;
    float acc[8][4] = {};
    const int wrow = wid * 16;

    for (int kb = 0; kb < S_; kb += 64) {
        __syncthreads();
        {
            int row = tid >> 2;
            int cb  = (tid & 3) * 16;
            const float4* ks = (const float4*)&kp[(size_t)(kb + row) * HD_ + cb];
            const float4* vs = (const float4*)&vp[(size_t)(kb + row) * HD_ + cb];
            #pragma unroll
            for (int j = 0; j < 4; j++) {
                *(float4*)&Ks[row*68 + cb + j*4] = cvt4(ks[j]);
                *(float4*)&Vs[row*68 + cb + j*4] = cvt4(vs[j]);
            }
        }
        __syncthreads();

        // S = Q K^T : warp tile 16 x 64
        float s[8][4] = {};
        #pragma unroll
        for (int ksd = 0; ksd < 8; ksd++) {
            uint32_t a0 = __float_as_uint(Qs[(wrow+g  )*68 + ksd*8 + tig    ]);
            uint32_t a1 = __float_as_uint(Qs[(wrow+g+8)*68 + ksd*8 + tig    ]);
            uint32_t a2 = __float_as_uint(Qs[(wrow+g  )*68 + ksd*8 + tig + 4]);
            uint32_t a3 = __float_as_uint(Qs[(wrow+g+8)*68 + ksd*8 + tig + 4]);
            #pragma unroll
            for (int nt = 0; nt < 8; nt++) {
                uint32_t b0 = __float_as_uint(Ks[(nt*8+g)*68 + ksd*8 + tig    ]);
                uint32_t b1 = __float_as_uint(Ks[(nt*8+g)*68 + ksd*8 + tig + 4]);
                mma8(s[nt], a0, a1, a2, a3, b0, b1);
            }
        }

        // Online softmax. Thread owns rows (wrow+g) and (wrow+g+8), cols nt*8+tig*2+{0,1}
        float rm0 = -1e30f, rm1 = -1e30f;
        #pragma unroll
        for (int nt = 0; nt < 8; nt++) {
            rm0 = fmaxf(rm0, fmaxf(s[nt][0], s[nt][1]));
            rm1 = fmaxf(rm1, fmaxf(s[nt][2], s[nt][3]));
        }
        rm0 = fmaxf(rm0, __shfl_xor_sync(0xffffffffu, rm0, 1));
        rm0 = fmaxf(rm0, __shfl_xor_sync(0xffffffffu, rm0, 2));
        rm1 = fmaxf(rm1, __shfl_xor_sync(0xffffffffu, rm1, 1));
        rm1 = fmaxf(rm1, __shfl_xor_sync(0xffffffffu, rm1, 2));

        float nm0 = fmaxf(m0, rm0), nm1 = fmaxf(m1, rm1);
        float al0 = __expf(m0 - nm0), al1 = __expf(m1 - nm1);
        m0 = nm0; m1 = nm1;

        float sum0 = 0.f, sum1 = 0.f;
        #pragma unroll
        for (int nt = 0; nt < 8; nt++) {
            float p0 = __expf(s[nt][0] - nm0);
            float p1 = __expf(s[nt][1] - nm0);
            float p2 = __expf(s[nt][2] - nm1);
            float p3 = __expf(s[nt][3] - nm1);
            sum0 += p0 + p1; sum1 += p2 + p3;
            int col = nt*8 + tig*2;
            Ps[(wrow+g  )*68 + col    ] = f2tff(p0);
            Ps[(wrow+g  )*68 + col + 1] = f2tff(p1);
            Ps[(wrow+g+8)*68 + col    ] = f2tff(p2);
            Ps[(wrow+g+8)*68 + col + 1] = f2tff(p3);
        }
        sum0 += __shfl_xor_sync(0xffffffffu, sum0, 1);
        sum0 += __shfl_xor_sync(0xffffffffu, sum0, 2);
        sum1 += __shfl_xor_sync(0xffffffffu, sum1, 1);
        sum1 += __shfl_xor_sync(0xffffffffu, sum1, 2);
        l0 = l0 * al0 + sum0;
        l1 = l1 * al1 + sum1;

        #pragma unroll
        for (int nt = 0; nt < 8; nt++) {
            acc[nt][0] *= al0; acc[nt][1] *= al0;
            acc[nt][2] *= al1; acc[nt][3] *= al1;
        }
        __syncwarp();

        // acc += P * V : warp tile 16 x 64, k = 64 kv positions
        #pragma unroll
        for (int ksd = 0; ksd < 8; ksd++) {
            uint32_t a0 = __float_as_uint(Ps[(wrow+g  )*68 + ksd*8 + tig    ]);
            uint32_t a1 = __float_as_uint(Ps[(wrow+g+8)*68 + ksd*8 + tig    ]);
            uint32_t a2 = __float_as_uint(Ps[(wrow+g  )*68 + ksd*8 + tig + 4]);
            uint32_t a3 = __float_as_uint(Ps[(wrow+g+8)*68 + ksd*8 + tig + 4]);
            #pragma unroll
            for (int nt = 0; nt < 8; nt++) {
                uint32_t b0 = __float_as_uint(Vs[(ksd*8+tig  )*68 + nt*8 + g]);
                uint32_t b1 = __float_as_uint(Vs[(ksd*8+tig+4)*68 + nt*8 + g]);
                mma8(acc[nt], a0, a1, a2, a3, b0, b1);
            }
        }
    }

    // Epilogue: normalize and store in concat layout
    float inv0 = 1.0f / l0, inv1 = 1.0f / l1;
    int s_row0 = q0 + wrow + g;
    int s_row1 = s_row0 + 8;
    #pragma unroll
    for (int nt = 0; nt < 8; nt++) {
        int col = h*64 + nt*8 + tig*2;
        float2 v0, v1;
        v0.x = acc[nt][0]*inv0; v0.y = acc[nt][1]*inv0;
        v1.x = acc[nt][2]*inv1; v1.y = acc[nt][3]*inv1;
        *(float2*)&g_att[(size_t)(b*S_ + s_row0)*D_ + col] = v0;
        *(float2*)&g_att[(size_t)(b*S_ + s_row1)*D_ + col] = v1;
    }
}

// ---------------------------------------------------------------------------
extern "C" void kernel_launch(void* const* d_in, const int* in_sizes, int n_in,
                              void* d_out, int out_size)
{
    const float* V  = (const float*)d_in[0];
    const float* K  = (const float*)d_in[1];
    const float* Q  = (const float*)d_in[2];
    const float* Wv = (const float*)d_in[3];
    const float* bv = (const float*)d_in[4];
    const float* Wk = (const float*)d_in[5];
    const float* bk = (const float*)d_in[6];
    const float* Wq = (const float*)d_in[7];
    const float* bq = (const float*)d_in[8];
    const float* Wo = (const float*)d_in[9];
    const float* bo = (const float*)d_in[10];
    float* out = (float*)d_out;

    (void)in_sizes; (void)n_in; (void)out_size;

    float* gq; cudaGetSymbolAddress((void**)&gq, g_q);
    float* gk; cudaGetSymbolAddress((void**)&gk, g_k);
    float* gv; cudaGetSymbolAddress((void**)&gv, g_v);
    float* ga; cudaGetSymbolAddress((void**)&ga, g_att);

    dim3 gg(D_/128, MROWS/128);   // (8, 32)
    gemm_tf32<<<gg, 256>>>(Q, Wq, bq, gq, 1);
    gemm_tf32<<<gg, 256>>>(K, Wk, bk, gk, 1);
    gemm_tf32<<<gg, 256>>>(V, Wv, bv, gv, 1);

    const int smem = (128*68 + 128*68 + 64*68 + 64*68) * (int)sizeof(float); // 104448
    cudaFuncSetAttribute(attn_tc, cudaFuncAttributeMaxDynamicSharedMemorySize, smem);
    dim3 ga_grid(S_/128, B_*H_);  // (16, 32)
    attn_tc<<<ga_grid, 256, smem>>>();

    gemm_tf32<<<gg, 256>>>(ga, Wo, bo, out, 0);
}